// round 4
// baseline (speedup 1.0000x reference)
#include <cuda_runtime.h>

#define N_RAYS   (1 << 20)
#define T_ITERS  4
#define NPTS     8
#define DIM      64
#define IN_DIM   24
#define INF_F    1e9f

typedef unsigned long long ull;

// ---- packed f32x2 helpers (Blackwell fp32x2 path: 2x scalar FFMA throughput) ----
__device__ __forceinline__ ull pack2(float lo, float hi) {
    ull r; asm("mov.b64 %0, {%1, %2};" : "=l"(r) : "f"(lo), "f"(hi)); return r;
}
__device__ __forceinline__ void unpack2(ull v, float& lo, float& hi) {
    asm("mov.b64 {%0, %1}, %2;" : "=f"(lo), "=f"(hi) : "l"(v));
}
__device__ __forceinline__ void fma2(ull& d, ull a, ull b) {
    asm("fma.rn.f32x2 %0, %1, %2, %0;" : "+l"(d) : "l"(a), "l"(b));
}

struct __align__(16) SmemWeights {
    float  W0[IN_DIM][DIM];     // 6 KB
    float  Ws[2][DIM][DIM];     // 32 KB
    float  b0[DIM];
    float  bs[2][DIM];
    float  g[2][DIM];
    float  beta[2][DIM];
    float2 head[DIM];           // {Wc[k], Wd[k]} interleaved for packed head fma
    float  isc[3];
    float  off[3];
    float  bc, bd;
};

// minBlocksPerMultiprocessor=12 caps regs at ~170 (true peak need ~145) -> no spills
__global__ __launch_bounds__(128, 12) void nbvh_kernel(
    const float* __restrict__ orig, const float* __restrict__ vec,
    const unsigned int* __restrict__ masks,   // bool materialized as 4-byte words
    const float* __restrict__ t1, const float* __restrict__ t2,
    const float* __restrict__ mesh_min, const float* __restrict__ mesh_max,
    const float* __restrict__ W0, const float* __restrict__ b0,
    const float* __restrict__ ln_g, const float* __restrict__ ln_b,
    const float* __restrict__ Ws, const float* __restrict__ bs,
    const float* __restrict__ Wc, const float* __restrict__ bc,
    const float* __restrict__ Wd, const float* __restrict__ bd,
    float* __restrict__ out, int two_part)
{
    __shared__ SmemWeights sm;
    const int tid = threadIdx.x;

    // ---- cooperative weight staging ----
    for (int i = tid; i < IN_DIM * DIM; i += blockDim.x) ((float*)sm.W0)[i] = W0[i];
    for (int i = tid; i < 2 * DIM * DIM; i += blockDim.x) ((float*)sm.Ws)[i] = Ws[i];
    for (int i = tid; i < DIM; i += blockDim.x) {
        sm.b0[i]   = b0[i];
        sm.head[i] = make_float2(Wc[i], Wd[i]);
    }
    for (int i = tid; i < 2 * DIM; i += blockDim.x) {
        ((float*)sm.bs)[i]   = bs[i];
        ((float*)sm.g)[i]    = ln_g[i];
        ((float*)sm.beta)[i] = ln_b[i];
    }
    if (tid < 3) {
        float mn = mesh_min[tid], mx = mesh_max[tid];
        float min_infl = mn - 0.5f * (mx - mn);
        float scale    = 2.0f * (mx - mn);     // max_infl - min_infl
        float is       = 1.0f / scale;
        sm.isc[tid] = is;
        sm.off[tid] = -min_infl * is;          // x*isc + off == (x - min_infl)/scale
    }
    if (tid == 0) { sm.bc = bc[0]; sm.bd = bd[0]; }
    __syncthreads();

    const int r = blockIdx.x * blockDim.x + tid;
    if (r >= N_RAYS) return;

    const float o0 = orig[3 * r], o1 = orig[3 * r + 1], o2 = orig[3 * r + 2];
    const float v0 = vec[3 * r],  v1 = vec[3 * r + 1],  v2 = vec[3 * r + 2];
    const float iscx = sm.isc[0], iscy = sm.isc[1], iscz = sm.isc[2];
    const float offx = sm.off[0], offy = sm.off[1], offz = sm.off[2];

    float dist = INF_F;

    #pragma unroll 1
    for (int it = 0; it < T_ITERS; ++it) {
        const bool  m   = masks[it * N_RAYS + r] != 0u;
        const float ct1 = t1[it * N_RAYS + r];
        const float ct2 = t2[it * N_RAYS + r];

        const float po0 = fmaf(v0, ct1, o0);
        const float po1 = fmaf(v1, ct1, o1);
        const float po2 = fmaf(v2, ct1, o2);
        const float dt  = ct2 - ct1;
        const float pv0 = v0 * dt, pv1 = v1 * dt, pv2 = v2 * dt;

        // ---- build normalized 24-d input ----
        float x[IN_DIM];
        #pragma unroll
        for (int k = 0; k < NPTS; ++k) {
            const float t = (float)k * (1.0f / 7.0f);
            const float px = fmaf(pv0, t, po0);
            const float py = fmaf(pv1, t, po1);
            const float pz = fmaf(pv2, t, po2);
            x[3 * k + 0] = fmaf(px, iscx, offx);
            x[3 * k + 1] = fmaf(py, iscy, offy);
            x[3 * k + 2] = fmaf(pz, iscz, offz);
        }

        // ---- layer 0: [24] @ W0[24,64] + b0 ----
        ull acc[DIM / 2];
        {
            const ull* bb = (const ull*)sm.b0;
            #pragma unroll
            for (int q = 0; q < DIM / 2; ++q) acc[q] = bb[q];
        }
        #pragma unroll 8
        for (int k = 0; k < IN_DIM; ++k) {
            const ull a = pack2(x[k], x[k]);
            const ulonglong2* w = (const ulonglong2*)sm.W0[k];
            #pragma unroll
            for (int q = 0; q < 16; ++q) {
                const ulonglong2 ww = w[q];
                fma2(acc[2 * q + 0], a, ww.x);
                fma2(acc[2 * q + 1], a, ww.y);
            }
        }
        float act[DIM];
        #pragma unroll
        for (int q = 0; q < DIM / 2; ++q) unpack2(acc[q], act[2 * q], act[2 * q + 1]);

        // ---- 2 hidden layers: relu -> layernorm -> matmul ----
        #pragma unroll 1
        for (int L = 0; L < 2; ++L) {
            float mu = 0.f;
            #pragma unroll
            for (int k = 0; k < DIM; ++k) { act[k] = fmaxf(act[k], 0.f); mu += act[k]; }
            mu *= (1.0f / DIM);
            float var = 0.f;
            #pragma unroll
            for (int k = 0; k < DIM; ++k) { const float d = act[k] - mu; var = fmaf(d, d, var); }
            var *= (1.0f / DIM);
            const float rs = rsqrtf(var + 1e-5f);
            #pragma unroll
            for (int k = 0; k < DIM; ++k)
                act[k] = fmaf((act[k] - mu) * rs, sm.g[L][k], sm.beta[L][k]);

            const ull* bb = (const ull*)sm.bs[L];
            #pragma unroll
            for (int q = 0; q < DIM / 2; ++q) acc[q] = bb[q];
            #pragma unroll 8
            for (int k = 0; k < DIM; ++k) {
                const ull a = pack2(act[k], act[k]);
                const ulonglong2* w = (const ulonglong2*)sm.Ws[L][k];
                #pragma unroll
                for (int q = 0; q < 16; ++q) {
                    const ulonglong2 ww = w[q];
                    fma2(acc[2 * q + 0], a, ww.x);
                    fma2(acc[2 * q + 1], a, ww.y);
                }
            }
            #pragma unroll
            for (int q = 0; q < DIM / 2; ++q) unpack2(acc[q], act[2 * q], act[2 * q + 1]);
        }

        // ---- final relu + two heads as one packed dot ----
        ull h = pack2(sm.bc, sm.bd);
        const ull* hw = (const ull*)sm.head;
        #pragma unroll 8
        for (int k = 0; k < DIM; ++k) {
            const float a = fmaxf(act[k], 0.f);
            fma2(h, pack2(a, a), hw[k]);
        }
        float cls, dvc;
        unpack2(h, cls, dvc);

        // upd = mask & (hit>0) & (dv < dist); dv = dvc + ct1
        if (m && cls > 0.f) {
            const float dv = dvc + ct1;
            if (dv < dist) dist = dv;
        }
    }

    if (dist == INF_F) dist = 0.f;
    if (two_part) {
        out[r]          = (dist > 0.f) ? 1.f : 0.f;
        out[N_RAYS + r] = dist;
    } else {
        out[r] = dist;
    }
}

extern "C" void kernel_launch(void* const* d_in, const int* in_sizes, int n_in,
                              void* d_out, int out_size) {
    const float* orig      = (const float*)d_in[0];
    const float* vec       = (const float*)d_in[1];
    const unsigned int* masks = (const unsigned int*)d_in[2];   // bool[T,N] as 4-byte words
    /* d_in[3] = bbox_idxs (unused by reference) */
    const float* t1        = (const float*)d_in[4];
    const float* t2        = (const float*)d_in[5];
    const float* mesh_min  = (const float*)d_in[6];
    const float* mesh_max  = (const float*)d_in[7];
    const float* W0        = (const float*)d_in[8];
    const float* b0        = (const float*)d_in[9];
    const float* ln_g      = (const float*)d_in[10];
    const float* ln_b      = (const float*)d_in[11];
    const float* Ws        = (const float*)d_in[12];
    const float* bs        = (const float*)d_in[13];
    const float* Wc        = (const float*)d_in[14];
    const float* bc        = (const float*)d_in[15];
    const float* Wd        = (const float*)d_in[16];
    const float* bd        = (const float*)d_in[17];

    const int two_part = (out_size >= 2 * N_RAYS) ? 1 : 0;

    nbvh_kernel<<<N_RAYS / 128, 128>>>(
        orig, vec, masks, t1, t2, mesh_min, mesh_max,
        W0, b0, ln_g, ln_b, Ws, bs, Wc, bc, Wd, bd,
        (float*)d_out, two_part);
}

// round 5
// speedup vs baseline: 1.1672x; 1.1672x over previous
#include <cuda_runtime.h>

#define N_RAYS   (1 << 20)
#define T_ITERS  4
#define NPTS     8
#define DIM      64
#define IN_DIM   24
#define INF_F    1e9f

typedef unsigned long long ull;

// ---- packed f32x2 helpers ----
__device__ __forceinline__ ull pack2(float lo, float hi) {
    ull r; asm("mov.b64 %0, {%1, %2};" : "=l"(r) : "f"(lo), "f"(hi)); return r;
}
__device__ __forceinline__ void unpack2(ull v, float& lo, float& hi) {
    asm("mov.b64 {%0, %1}, %2;" : "=f"(lo), "=f"(hi) : "l"(v));
}
__device__ __forceinline__ void fma2(ull& d, ull a, ull b) {
    asm("fma.rn.f32x2 %0, %1, %2, %0;" : "+l"(d) : "l"(a), "l"(b));
}

struct __align__(16) SmemWeights {
    float  W0[IN_DIM][DIM];     // 6 KB
    float  Ws[2][DIM][DIM];     // 32 KB
    float  b0[DIM];
    float  bs[2][DIM];
    float  g[2][DIM];
    float  beta[2][DIM];
    float2 head[DIM];           // {Wc[k], Wd[k]}
    float  isc[3];
    float  off[3];
    float  bc, bd;
};

// pair exchange: each thread owns 16 ull (32 output cols); rebuild full 64-col act
__device__ __forceinline__ void pair_exchange(const ull* acc, int p, float* act) {
    #pragma unroll
    for (int q = 0; q < 16; ++q) {
        const ull other = __shfl_xor_sync(0xFFFFFFFFu, acc[q], 1);
        const ull lo = p ? other : acc[q];   // cols [0,32)
        const ull hi = p ? acc[q] : other;   // cols [32,64)
        unpack2(lo, act[2 * q],      act[2 * q + 1]);
        unpack2(hi, act[32 + 2 * q], act[32 + 2 * q + 1]);
    }
}

// 2 threads per ray; per-thread live state ~96 regs -> full unroll, no spills
__global__ __launch_bounds__(256, 5) void nbvh_kernel(
    const float* __restrict__ orig, const float* __restrict__ vec,
    const unsigned int* __restrict__ masks,   // bool materialized as 4-byte words
    const float* __restrict__ t1, const float* __restrict__ t2,
    const float* __restrict__ mesh_min, const float* __restrict__ mesh_max,
    const float* __restrict__ W0, const float* __restrict__ b0,
    const float* __restrict__ ln_g, const float* __restrict__ ln_b,
    const float* __restrict__ Ws, const float* __restrict__ bs,
    const float* __restrict__ Wc, const float* __restrict__ bc,
    const float* __restrict__ Wd, const float* __restrict__ bd,
    float* __restrict__ out, int two_part)
{
    __shared__ SmemWeights sm;
    const int tid = threadIdx.x;

    // ---- cooperative weight staging ----
    for (int i = tid; i < IN_DIM * DIM; i += 256) ((float*)sm.W0)[i] = W0[i];
    for (int i = tid; i < 2 * DIM * DIM; i += 256) ((float*)sm.Ws)[i] = Ws[i];
    if (tid < DIM) {
        sm.b0[tid]   = b0[tid];
        sm.head[tid] = make_float2(Wc[tid], Wd[tid]);
    }
    if (tid >= 64 && tid < 64 + 2 * DIM) {
        const int i = tid - 64;
        ((float*)sm.bs)[i]   = bs[i];
        ((float*)sm.g)[i]    = ln_g[i];
        ((float*)sm.beta)[i] = ln_b[i];
    }
    if (tid >= 192 && tid < 195) {
        const int c = tid - 192;
        float mn = mesh_min[c], mx = mesh_max[c];
        float min_infl = mn - 0.5f * (mx - mn);
        float is       = 1.0f / (2.0f * (mx - mn));
        sm.isc[c] = is;
        sm.off[c] = -min_infl * is;
    }
    if (tid == 195) { sm.bc = bc[0]; sm.bd = bd[0]; }
    __syncthreads();

    const int p = tid & 1;                        // output-half index
    const int r = blockIdx.x * 128 + (tid >> 1);  // ray index

    const float o0 = orig[3 * r], o1 = orig[3 * r + 1], o2 = orig[3 * r + 2];
    const float v0 = vec[3 * r],  v1 = vec[3 * r + 1],  v2 = vec[3 * r + 2];
    const float iscx = sm.isc[0], iscy = sm.isc[1], iscz = sm.isc[2];
    const float offx = sm.off[0], offy = sm.off[1], offz = sm.off[2];

    float dist = INF_F;

    #pragma unroll 1
    for (int it = 0; it < T_ITERS; ++it) {
        const bool  m   = masks[it * N_RAYS + r] != 0u;
        const float ct1 = t1[it * N_RAYS + r];
        const float ct2 = t2[it * N_RAYS + r];

        const float po0 = fmaf(v0, ct1, o0);
        const float po1 = fmaf(v1, ct1, o1);
        const float po2 = fmaf(v2, ct1, o2);
        const float dt  = ct2 - ct1;
        const float pv0 = v0 * dt, pv1 = v1 * dt, pv2 = v2 * dt;

        // ---- normalized 24-d input ----
        float x[IN_DIM];
        #pragma unroll
        for (int k = 0; k < NPTS; ++k) {
            const float t = (float)k * (1.0f / 7.0f);
            const float px = fmaf(pv0, t, po0);
            const float py = fmaf(pv1, t, po1);
            const float pz = fmaf(pv2, t, po2);
            x[3 * k + 0] = fmaf(px, iscx, offx);
            x[3 * k + 1] = fmaf(py, iscy, offy);
            x[3 * k + 2] = fmaf(pz, iscz, offz);
        }

        // ---- layer 0: this thread's 32-col half ----
        ull acc[16];
        {
            const ull* bb = (const ull*)sm.b0 + p * 16;
            #pragma unroll
            for (int q = 0; q < 16; ++q) acc[q] = bb[q];
        }
        #pragma unroll
        for (int k = 0; k < IN_DIM; ++k) {
            const ull a = pack2(x[k], x[k]);
            const ulonglong2* w = (const ulonglong2*)sm.W0[k] + p * 8;
            #pragma unroll
            for (int q = 0; q < 8; ++q) {
                const ulonglong2 ww = w[q];
                fma2(acc[2 * q + 0], a, ww.x);
                fma2(acc[2 * q + 1], a, ww.y);
            }
        }

        float act[DIM];
        pair_exchange(acc, p, act);

        // ---- 2 hidden layers: relu -> layernorm -> half-matmul -> exchange ----
        #pragma unroll 1
        for (int L = 0; L < 2; ++L) {
            float mu = 0.f;
            #pragma unroll
            for (int k = 0; k < DIM; ++k) { act[k] = fmaxf(act[k], 0.f); mu += act[k]; }
            mu *= (1.0f / DIM);
            float var = 0.f;
            #pragma unroll
            for (int k = 0; k < DIM; ++k) { const float d = act[k] - mu; var = fmaf(d, d, var); }
            var *= (1.0f / DIM);
            const float rs = rsqrtf(var + 1e-5f);
            #pragma unroll
            for (int k = 0; k < DIM; ++k)
                act[k] = fmaf((act[k] - mu) * rs, sm.g[L][k], sm.beta[L][k]);

            {
                const ull* bb = (const ull*)sm.bs[L] + p * 16;
                #pragma unroll
                for (int q = 0; q < 16; ++q) acc[q] = bb[q];
            }
            #pragma unroll
            for (int k = 0; k < DIM; ++k) {
                const ull a = pack2(act[k], act[k]);
                const ulonglong2* w = (const ulonglong2*)sm.Ws[L][k] + p * 8;
                #pragma unroll
                for (int q = 0; q < 8; ++q) {
                    const ulonglong2 ww = w[q];
                    fma2(acc[2 * q + 0], a, ww.x);
                    fma2(acc[2 * q + 1], a, ww.y);
                }
            }
            pair_exchange(acc, p, act);
        }

        // ---- final relu + both heads as one packed dot (redundant in pair) ----
        ull h = pack2(sm.bc, sm.bd);
        const ull* hw = (const ull*)sm.head;
        #pragma unroll
        for (int k = 0; k < DIM; ++k) {
            const float a = fmaxf(act[k], 0.f);
            fma2(h, pack2(a, a), hw[k]);
        }
        float cls, dvc;
        unpack2(h, cls, dvc);

        if (m && cls > 0.f) {
            const float dv = dvc + ct1;
            if (dv < dist) dist = dv;
        }
    }

    if (p == 0) {
        if (dist == INF_F) dist = 0.f;
        if (two_part) {
            out[r]          = (dist > 0.f) ? 1.f : 0.f;
            out[N_RAYS + r] = dist;
        } else {
            out[r] = dist;
        }
    }
}

extern "C" void kernel_launch(void* const* d_in, const int* in_sizes, int n_in,
                              void* d_out, int out_size) {
    const float* orig      = (const float*)d_in[0];
    const float* vec       = (const float*)d_in[1];
    const unsigned int* masks = (const unsigned int*)d_in[2];   // bool[T,N] as 4-byte words
    /* d_in[3] = bbox_idxs (unused by reference) */
    const float* t1        = (const float*)d_in[4];
    const float* t2        = (const float*)d_in[5];
    const float* mesh_min  = (const float*)d_in[6];
    const float* mesh_max  = (const float*)d_in[7];
    const float* W0        = (const float*)d_in[8];
    const float* b0        = (const float*)d_in[9];
    const float* ln_g      = (const float*)d_in[10];
    const float* ln_b      = (const float*)d_in[11];
    const float* Ws        = (const float*)d_in[12];
    const float* bs        = (const float*)d_in[13];
    const float* Wc        = (const float*)d_in[14];
    const float* bc        = (const float*)d_in[15];
    const float* Wd        = (const float*)d_in[16];
    const float* bd        = (const float*)d_in[17];

    const int two_part = (out_size >= 2 * N_RAYS) ? 1 : 0;

    nbvh_kernel<<<N_RAYS / 128, 256>>>(
        orig, vec, masks, t1, t2, mesh_min, mesh_max,
        W0, b0, ln_g, ln_b, Ws, bs, Wc, bc, Wd, bd,
        (float*)d_out, two_part);
}

// round 6
// speedup vs baseline: 4.8153x; 4.1255x over previous
#include <cuda_runtime.h>

#define N_RAYS   (1 << 20)
#define T_ITERS  4
#define NPTS     8
#define DIM      64
#define IN_DIM   24
#define INF_F    1e9f

typedef unsigned long long ull;

// ---- packed f32x2 helpers ----
__device__ __forceinline__ ull pack2(float lo, float hi) {
    ull r; asm("mov.b64 %0, {%1, %2};" : "=l"(r) : "f"(lo), "f"(hi)); return r;
}
__device__ __forceinline__ void unpack2(ull v, float& lo, float& hi) {
    asm("mov.b64 {%0, %1}, %2;" : "=f"(lo), "=f"(hi) : "l"(v));
}
__device__ __forceinline__ void fma2(ull& d, ull a, ull b) {
    asm("fma.rn.f32x2 %0, %1, %2, %0;" : "+l"(d) : "l"(a), "l"(b));
}

struct __align__(16) SmemWeights {
    float  W0[IN_DIM][DIM];     // 6 KB
    float  Ws[2][DIM][DIM];     // 32 KB
    float  b0[DIM];
    float  bs[2][DIM];
    float  g[2][DIM];
    float  beta[2][DIM];
    float2 head[DIM];           // {Wc[k], Wd[k]}
    float  isc[3];
    float  off[3];
    float  bc, bd;
};

// pair exchange: each thread owns 16 ull (32 output cols); rebuild full 64-col act
__device__ __forceinline__ void pair_exchange(const ull (&acc)[16], int p, float (&act)[DIM]) {
    #pragma unroll
    for (int q = 0; q < 16; ++q) {
        const ull other = __shfl_xor_sync(0xFFFFFFFFu, acc[q], 1);
        const ull lo = p ? other : acc[q];   // cols [0,32)
        const ull hi = p ? acc[q] : other;   // cols [32,64)
        unpack2(lo, act[2 * q],      act[2 * q + 1]);
        unpack2(hi, act[32 + 2 * q], act[32 + 2 * q + 1]);
    }
}

// 2 threads per ray. NO minBlocks cap: capping below ptxas's appetite makes it
// demote act/acc to local memory wholesale (R4/R5 evidence: regs 40-48, DRAM 60%).
__global__ __launch_bounds__(256) void nbvh_kernel(
    const float* __restrict__ orig, const float* __restrict__ vec,
    const unsigned int* __restrict__ masks,   // bool materialized as 4-byte words
    const float* __restrict__ t1, const float* __restrict__ t2,
    const float* __restrict__ mesh_min, const float* __restrict__ mesh_max,
    const float* __restrict__ W0, const float* __restrict__ b0,
    const float* __restrict__ ln_g, const float* __restrict__ ln_b,
    const float* __restrict__ Ws, const float* __restrict__ bs,
    const float* __restrict__ Wc, const float* __restrict__ bc,
    const float* __restrict__ Wd, const float* __restrict__ bd,
    float* __restrict__ out, int two_part)
{
    __shared__ SmemWeights sm;
    const int tid = threadIdx.x;

    // ---- cooperative weight staging ----
    for (int i = tid; i < IN_DIM * DIM; i += 256) ((float*)sm.W0)[i] = W0[i];
    for (int i = tid; i < 2 * DIM * DIM; i += 256) ((float*)sm.Ws)[i] = Ws[i];
    if (tid < DIM) {
        sm.b0[tid]   = b0[tid];
        sm.head[tid] = make_float2(Wc[tid], Wd[tid]);
    }
    if (tid >= 64 && tid < 64 + 2 * DIM) {
        const int i = tid - 64;
        ((float*)sm.bs)[i]   = bs[i];
        ((float*)sm.g)[i]    = ln_g[i];
        ((float*)sm.beta)[i] = ln_b[i];
    }
    if (tid >= 192 && tid < 195) {
        const int c = tid - 192;
        float mn = mesh_min[c], mx = mesh_max[c];
        float min_infl = mn - 0.5f * (mx - mn);
        float is       = 1.0f / (2.0f * (mx - mn));
        sm.isc[c] = is;
        sm.off[c] = -min_infl * is;
    }
    if (tid == 195) { sm.bc = bc[0]; sm.bd = bd[0]; }
    __syncthreads();

    const int p = tid & 1;                        // output-half index
    const int r = blockIdx.x * 128 + (tid >> 1);  // ray index

    const float o0 = orig[3 * r], o1 = orig[3 * r + 1], o2 = orig[3 * r + 2];
    const float v0 = vec[3 * r],  v1 = vec[3 * r + 1],  v2 = vec[3 * r + 2];
    const float iscx = sm.isc[0], iscy = sm.isc[1], iscz = sm.isc[2];
    const float offx = sm.off[0], offy = sm.off[1], offz = sm.off[2];

    float dist = INF_F;

    #pragma unroll 1
    for (int it = 0; it < T_ITERS; ++it) {
        const bool  m   = masks[it * N_RAYS + r] != 0u;
        const float ct1 = t1[it * N_RAYS + r];
        const float ct2 = t2[it * N_RAYS + r];

        const float po0 = fmaf(v0, ct1, o0);
        const float po1 = fmaf(v1, ct1, o1);
        const float po2 = fmaf(v2, ct1, o2);
        const float dt  = ct2 - ct1;
        const float pv0 = v0 * dt, pv1 = v1 * dt, pv2 = v2 * dt;

        // ---- normalized 24-d input ----
        float x[IN_DIM];
        #pragma unroll
        for (int k = 0; k < NPTS; ++k) {
            const float t = (float)k * (1.0f / 7.0f);
            const float px = fmaf(pv0, t, po0);
            const float py = fmaf(pv1, t, po1);
            const float pz = fmaf(pv2, t, po2);
            x[3 * k + 0] = fmaf(px, iscx, offx);
            x[3 * k + 1] = fmaf(py, iscy, offy);
            x[3 * k + 2] = fmaf(pz, iscz, offz);
        }

        // ---- layer 0: this thread's 32-col half ----
        ull acc[16];
        {
            const ull* bb = (const ull*)sm.b0 + p * 16;
            #pragma unroll
            for (int q = 0; q < 16; ++q) acc[q] = bb[q];
        }
        #pragma unroll
        for (int k = 0; k < IN_DIM; ++k) {
            const ull a = pack2(x[k], x[k]);
            const ulonglong2* w = (const ulonglong2*)sm.W0[k] + p * 8;
            #pragma unroll
            for (int q = 0; q < 8; ++q) {
                const ulonglong2 ww = w[q];
                fma2(acc[2 * q + 0], a, ww.x);
                fma2(acc[2 * q + 1], a, ww.y);
            }
        }

        float act[DIM];
        pair_exchange(acc, p, act);

        // ---- 2 hidden layers: relu -> layernorm -> half-matmul ----
        #pragma unroll 1
        for (int L = 0; L < 2; ++L) {
            float mu = 0.f;
            #pragma unroll
            for (int k = 0; k < DIM; ++k) { act[k] = fmaxf(act[k], 0.f); mu += act[k]; }
            mu *= (1.0f / DIM);
            float var = 0.f;
            #pragma unroll
            for (int k = 0; k < DIM; ++k) { const float d = act[k] - mu; var = fmaf(d, d, var); }
            var *= (1.0f / DIM);
            const float rs = rsqrtf(var + 1e-5f);
            #pragma unroll
            for (int k = 0; k < DIM; ++k)
                act[k] = fmaf((act[k] - mu) * rs, sm.g[L][k], sm.beta[L][k]);

            {
                const ull* bb = (const ull*)sm.bs[L] + p * 16;
                #pragma unroll
                for (int q = 0; q < 16; ++q) acc[q] = bb[q];
            }
            #pragma unroll
            for (int k = 0; k < DIM; ++k) {
                const ull a = pack2(act[k], act[k]);
                const ulonglong2* w = (const ulonglong2*)sm.Ws[L][k] + p * 8;
                #pragma unroll
                for (int q = 0; q < 8; ++q) {
                    const ulonglong2 ww = w[q];
                    fma2(acc[2 * q + 0], a, ww.x);
                    fma2(acc[2 * q + 1], a, ww.y);
                }
            }
            if (L == 0) pair_exchange(acc, p, act);
        }

        // ---- final relu + partial head dot over OWN 32 cols, then butterfly add ----
        // (avoids the third exchange: halves shuffle traffic and live state here)
        ull h = (p == 0) ? pack2(sm.bc, sm.bd) : pack2(0.f, 0.f);
        const ull* hw = (const ull*)sm.head + p * 32;
        #pragma unroll
        for (int q = 0; q < 16; ++q) {
            float a0, a1;
            unpack2(acc[q], a0, a1);
            a0 = fmaxf(a0, 0.f);
            a1 = fmaxf(a1, 0.f);
            fma2(h, pack2(a0, a0), hw[2 * q + 0]);
            fma2(h, pack2(a1, a1), hw[2 * q + 1]);
        }
        float cls, dvc;
        unpack2(h, cls, dvc);
        cls += __shfl_xor_sync(0xFFFFFFFFu, cls, 1);
        dvc += __shfl_xor_sync(0xFFFFFFFFu, dvc, 1);

        if (m && cls > 0.f) {
            const float dv = dvc + ct1;
            if (dv < dist) dist = dv;
        }
    }

    if (p == 0) {
        if (dist == INF_F) dist = 0.f;
        if (two_part) {
            out[r]          = (dist > 0.f) ? 1.f : 0.f;
            out[N_RAYS + r] = dist;
        } else {
            out[r] = dist;
        }
    }
}

extern "C" void kernel_launch(void* const* d_in, const int* in_sizes, int n_in,
                              void* d_out, int out_size) {
    const float* orig      = (const float*)d_in[0];
    const float* vec       = (const float*)d_in[1];
    const unsigned int* masks = (const unsigned int*)d_in[2];   // bool[T,N] as 4-byte words
    /* d_in[3] = bbox_idxs (unused by reference) */
    const float* t1        = (const float*)d_in[4];
    const float* t2        = (const float*)d_in[5];
    const float* mesh_min  = (const float*)d_in[6];
    const float* mesh_max  = (const float*)d_in[7];
    const float* W0        = (const float*)d_in[8];
    const float* b0        = (const float*)d_in[9];
    const float* ln_g      = (const float*)d_in[10];
    const float* ln_b      = (const float*)d_in[11];
    const float* Ws        = (const float*)d_in[12];
    const float* bs        = (const float*)d_in[13];
    const float* Wc        = (const float*)d_in[14];
    const float* bc        = (const float*)d_in[15];
    const float* Wd        = (const float*)d_in[16];
    const float* bd        = (const float*)d_in[17];

    const int two_part = (out_size >= 2 * N_RAYS) ? 1 : 0;

    nbvh_kernel<<<N_RAYS / 128, 256>>>(
        orig, vec, masks, t1, t2, mesh_min, mesh_max,
        W0, b0, ln_g, ln_b, Ws, bs, Wc, bc, Wd, bd,
        (float*)d_out, two_part);
}

// round 8
// speedup vs baseline: 12.6542x; 2.6279x over previous
#include <cuda_runtime.h>

#define N_RAYS   (1 << 20)
#define T_ITERS  4
#define DIM      64
#define IN_DIM   24
#define INF_F    1e9f
#define XST      260          // Xs row stride in floats (multiple of 4 for float4)
#define RAYS_PB  256
#define THREADS  128

typedef unsigned long long ull;

__device__ __forceinline__ ull pack2(float lo, float hi) {
    ull r; asm("mov.b64 %0, {%1, %2};" : "=l"(r) : "f"(lo), "f"(hi)); return r;
}
__device__ __forceinline__ void unpack2(ull v, float& lo, float& hi) {
    asm("mov.b64 {%0, %1}, %2;" : "=f"(lo), "=f"(hi) : "l"(v));
}
__device__ __forceinline__ void fma2(ull& d, ull a, ull b) {
    asm("fma.rn.f32x2 %0, %1, %2, %0;" : "+l"(d) : "l"(a), "l"(b));
}
__device__ __forceinline__ ull fma2v(ull a, ull b, ull c) {
    ull r; asm("fma.rn.f32x2 %0, %1, %2, %3;" : "=l"(r) : "l"(a), "l"(b), "l"(c)); return r;
}
__device__ __forceinline__ ull add2(ull a, ull b) {
    ull r; asm("add.rn.f32x2 %0, %1, %2;" : "=l"(r) : "l"(a), "l"(b)); return r;
}
__device__ __forceinline__ ull mul2(ull a, ull b) {
    ull r; asm("mul.rn.f32x2 %0, %1, %2;" : "=l"(r) : "l"(a), "l"(b)); return r;
}

struct SM {
    float  W0[IN_DIM][DIM];   // 6 KB
    float  Ws[2][DIM][DIM];   // 32 KB
    float  b0[DIM];
    float  bs[2][DIM];
    float  g[2][DIM];
    float  be[2][DIM];
    float2 head[DIM];         // {Wc, Wd}
    float  isc[3], off[3], bc, bd;
    float  Xs[DIM][XST];      // transposed activations: [feature][ray]
};

// GEMM step: acc[rr][c] (+)= Xs[k][8i+rr] * W[k][16j + 2c..]; acc packed over col pairs
template<int K>
__device__ __forceinline__ void gemm_tile(const float* __restrict__ Xs,
                                          const float* __restrict__ W,
                                          const float* __restrict__ bias,
                                          int i, int j, ull (&acc)[8][8])
{
    const ull* bu = (const ull*)(bias + 16 * j);
    #pragma unroll
    for (int c = 0; c < 8; ++c) {
        const ull b2 = bu[c];
        #pragma unroll
        for (int rr = 0; rr < 8; ++rr) acc[rr][c] = b2;
    }
    const float* arow = Xs + 8 * i;
    const float* brow = W + 16 * j;
    #pragma unroll 4
    for (int k = 0; k < K; ++k) {
        const float4 a0 = *(const float4*)(arow);
        const float4 a1 = *(const float4*)(arow + 4);
        const ulonglong2 w0 = ((const ulonglong2*)brow)[0];
        const ulonglong2 w1 = ((const ulonglong2*)brow)[1];
        const ulonglong2 w2 = ((const ulonglong2*)brow)[2];
        const ulonglong2 w3 = ((const ulonglong2*)brow)[3];
        const ull b[8] = { w0.x, w0.y, w1.x, w1.y, w2.x, w2.y, w3.x, w3.y };
        const float av[8] = { a0.x, a0.y, a0.z, a0.w, a1.x, a1.y, a1.z, a1.w };
        #pragma unroll
        for (int rr = 0; rr < 8; ++rr) {
            const ull au = pack2(av[rr], av[rr]);
            #pragma unroll
            for (int c = 0; c < 8; ++c) fma2(acc[rr][c], au, b[c]);
        }
        arow += XST;
        brow += DIM;
    }
}

__global__ __launch_bounds__(THREADS) void nbvh_kernel(
    const float* __restrict__ orig, const float* __restrict__ vec,
    const unsigned int* __restrict__ masks,
    const float* __restrict__ t1, const float* __restrict__ t2,
    const float* __restrict__ mesh_min, const float* __restrict__ mesh_max,
    const float* __restrict__ W0, const float* __restrict__ b0,
    const float* __restrict__ ln_g, const float* __restrict__ ln_b,
    const float* __restrict__ Ws, const float* __restrict__ bs,
    const float* __restrict__ Wc, const float* __restrict__ bc,
    const float* __restrict__ Wd, const float* __restrict__ bd,
    float* __restrict__ out, int two_part)
{
    extern __shared__ SM sm[];
    SM& s = sm[0];
    const int tid = threadIdx.x;

    // ---- weight staging ----
    for (int x = tid; x < IN_DIM * DIM; x += THREADS) ((float*)s.W0)[x] = W0[x];
    for (int x = tid; x < 2 * DIM * DIM; x += THREADS) ((float*)s.Ws)[x] = Ws[x];
    if (tid < DIM) {
        s.b0[tid]   = b0[tid];
        s.head[tid] = make_float2(Wc[tid], Wd[tid]);
    }
    for (int x = tid; x < 2 * DIM; x += THREADS) {
        ((float*)s.bs)[x] = bs[x];
        ((float*)s.g)[x]  = ln_g[x];
        ((float*)s.be)[x] = ln_b[x];
    }
    if (tid < 3) {
        float mn = mesh_min[tid], mx = mesh_max[tid];
        float min_infl = mn - 0.5f * (mx - mn);
        float is = 1.0f / (2.0f * (mx - mn));
        s.isc[tid] = is;
        s.off[tid] = -min_infl * is;
    }
    if (tid == 3) { s.bc = bc[0]; s.bd = bd[0]; }
    __syncthreads();

    const int j = tid & 3;          // col group: cols [16j, 16j+16)
    const int i = tid >> 2;         // ray group: rays [8i, 8i+8)
    const int blockRay = blockIdx.x * RAYS_PB;

    const float iscx = s.isc[0], iscy = s.isc[1], iscz = s.isc[2];
    const float offx = s.off[0], offy = s.off[1], offz = s.off[2];
    const float hbc = s.bc, hbd = s.bd;

    float dist[8];
    #pragma unroll
    for (int rr = 0; rr < 8; ++rr) dist[rr] = INF_F;

    #pragma unroll 1
    for (int it = 0; it < T_ITERS; ++it) {
        __syncthreads();   // previous iter's GEMM reads of Xs complete

        // ---- build inputs: 2 rays/thread into Xs[d][ray] ----
        #pragma unroll
        for (int sray = 0; sray < 2; ++sray) {
            const int lr = 2 * tid + sray;
            const int gr = blockRay + lr;
            const float o0 = orig[3 * gr], o1 = orig[3 * gr + 1], o2 = orig[3 * gr + 2];
            const float v0 = vec[3 * gr],  v1 = vec[3 * gr + 1],  v2 = vec[3 * gr + 2];
            const float ct1 = t1[it * N_RAYS + gr];
            const float ct2 = t2[it * N_RAYS + gr];
            const float po0 = fmaf(v0, ct1, o0);
            const float po1 = fmaf(v1, ct1, o1);
            const float po2 = fmaf(v2, ct1, o2);
            const float dt = ct2 - ct1;
            const float pv0 = v0 * dt, pv1 = v1 * dt, pv2 = v2 * dt;
            #pragma unroll
            for (int k = 0; k < 8; ++k) {
                const float t = (float)k * (1.0f / 7.0f);
                s.Xs[3 * k + 0][lr] = fmaf(fmaf(pv0, t, po0), iscx, offx);
                s.Xs[3 * k + 1][lr] = fmaf(fmaf(pv1, t, po1), iscy, offy);
                s.Xs[3 * k + 2][lr] = fmaf(fmaf(pv2, t, po2), iscz, offz);
            }
        }
        __syncthreads();

        ull acc[8][8];

        #pragma unroll 1
        for (int L = 0; L < 3; ++L) {
            if (L == 0)      gemm_tile<IN_DIM>(&s.Xs[0][0], &s.W0[0][0],    s.b0,    i, j, acc);
            else if (L == 1) gemm_tile<DIM>   (&s.Xs[0][0], &s.Ws[0][0][0], s.bs[0], i, j, acc);
            else             gemm_tile<DIM>   (&s.Xs[0][0], &s.Ws[1][0][0], s.bs[1], i, j, acc);

            if (L == 2) break;

            // ---- relu + layernorm on the register tile (reduce over 4 j-threads) ----
            const ull* gu  = (const ull*)(s.g[L]  + 16 * j);
            const ull* beu = (const ull*)(s.be[L] + 16 * j);
            #pragma unroll
            for (int rr = 0; rr < 8; ++rr) {
                // relu + partial sum
                ull sp = pack2(0.f, 0.f);
                #pragma unroll
                for (int c = 0; c < 8; ++c) {
                    float lo, hi;
                    unpack2(acc[rr][c], lo, hi);
                    lo = fmaxf(lo, 0.f); hi = fmaxf(hi, 0.f);
                    acc[rr][c] = pack2(lo, hi);
                    sp = add2(sp, acc[rr][c]);
                }
                float sl, sh;
                unpack2(sp, sl, sh);
                float sum = sl + sh;
                sum += __shfl_xor_sync(0xFFFFFFFFu, sum, 1);
                sum += __shfl_xor_sync(0xFFFFFFFFu, sum, 2);
                const float mu = sum * (1.0f / DIM);
                const ull negmu = pack2(-mu, -mu);
                ull vp = pack2(0.f, 0.f);
                #pragma unroll
                for (int c = 0; c < 8; ++c) {
                    const ull d = add2(acc[rr][c], negmu);
                    fma2(vp, d, d);
                }
                float vl, vh;
                unpack2(vp, vl, vh);
                float var = vl + vh;
                var += __shfl_xor_sync(0xFFFFFFFFu, var, 1);
                var += __shfl_xor_sync(0xFFFFFFFFu, var, 2);
                const float rs = rsqrtf(var * (1.0f / DIM) + 1e-5f);
                const ull rs2 = pack2(rs, rs);
                #pragma unroll
                for (int c = 0; c < 8; ++c) {
                    const ull d  = add2(acc[rr][c], negmu);
                    const ull rg = mul2(gu[c], rs2);
                    acc[rr][c] = fma2v(d, rg, beu[c]);
                }
            }

            // ---- write back transposed: Xs[16j + col][rays] ----
            __syncthreads();   // all warps done reading Xs for this GEMM
            #pragma unroll
            for (int c = 0; c < 8; ++c) {
                float fl[8], fh[8];
                #pragma unroll
                for (int rr = 0; rr < 8; ++rr) unpack2(acc[rr][c], fl[rr], fh[rr]);
                float* r0 = &s.Xs[16 * j + 2 * c][8 * i];
                float* r1 = &s.Xs[16 * j + 2 * c + 1][8 * i];
                *(float4*)(r0)     = make_float4(fl[0], fl[1], fl[2], fl[3]);
                *(float4*)(r0 + 4) = make_float4(fl[4], fl[5], fl[6], fl[7]);
                *(float4*)(r1)     = make_float4(fh[0], fh[1], fh[2], fh[3]);
                *(float4*)(r1 + 4) = make_float4(fh[4], fh[5], fh[6], fh[7]);
            }
            __syncthreads();
        }

        // ---- final relu + heads (partial over own 16 cols, butterfly over j) ----
        const ull* hwu = (const ull*)s.head + 16 * j;   // {Wc,Wd} per col
        const int gr8 = blockRay + 8 * i;
        const uint4 m0 = *(const uint4*)(masks + (size_t)it * N_RAYS + gr8);
        const uint4 m1 = *(const uint4*)(masks + (size_t)it * N_RAYS + gr8 + 4);
        const float4 t1a = *(const float4*)(t1 + (size_t)it * N_RAYS + gr8);
        const float4 t1b = *(const float4*)(t1 + (size_t)it * N_RAYS + gr8 + 4);
        const unsigned int mv[8] = { m0.x, m0.y, m0.z, m0.w, m1.x, m1.y, m1.z, m1.w };
        const float tv[8] = { t1a.x, t1a.y, t1a.z, t1a.w, t1b.x, t1b.y, t1b.z, t1b.w };

        #pragma unroll
        for (int rr = 0; rr < 8; ++rr) {
            ull h = pack2(0.f, 0.f);
            #pragma unroll
            for (int c = 0; c < 8; ++c) {
                float lo, hi;
                unpack2(acc[rr][c], lo, hi);
                lo = fmaxf(lo, 0.f); hi = fmaxf(hi, 0.f);
                fma2(h, pack2(lo, lo), hwu[2 * c]);
                fma2(h, pack2(hi, hi), hwu[2 * c + 1]);
            }
            h = add2(h, __shfl_xor_sync(0xFFFFFFFFu, h, 1));
            h = add2(h, __shfl_xor_sync(0xFFFFFFFFu, h, 2));
            float cls, dvc;
            unpack2(h, cls, dvc);
            cls += hbc; dvc += hbd;
            if (mv[rr] != 0u && cls > 0.f) {
                const float dv = dvc + tv[rr];
                if (dv < dist[rr]) dist[rr] = dv;
            }
        }
    }

    // ---- output (j==0 threads own the rays) ----
    if (j == 0) {
        #pragma unroll
        for (int rr = 0; rr < 8; ++rr) {
            const int gr = blockRay + 8 * i + rr;
            float d = dist[rr];
            if (d == INF_F) d = 0.f;
            if (two_part) {
                out[gr]          = (d > 0.f) ? 1.f : 0.f;
                out[N_RAYS + gr] = d;
            } else {
                out[gr] = d;
            }
        }
    }
}

extern "C" void kernel_launch(void* const* d_in, const int* in_sizes, int n_in,
                              void* d_out, int out_size) {
    const float* orig      = (const float*)d_in[0];
    const float* vec       = (const float*)d_in[1];
    const unsigned int* masks = (const unsigned int*)d_in[2];
    /* d_in[3] = bbox_idxs (unused) */
    const float* t1        = (const float*)d_in[4];
    const float* t2        = (const float*)d_in[5];
    const float* mesh_min  = (const float*)d_in[6];
    const float* mesh_max  = (const float*)d_in[7];
    const float* W0        = (const float*)d_in[8];
    const float* b0        = (const float*)d_in[9];
    const float* ln_g      = (const float*)d_in[10];
    const float* ln_b      = (const float*)d_in[11];
    const float* Ws        = (const float*)d_in[12];
    const float* bs        = (const float*)d_in[13];
    const float* Wc        = (const float*)d_in[14];
    const float* bc        = (const float*)d_in[15];
    const float* Wd        = (const float*)d_in[16];
    const float* bd        = (const float*)d_in[17];

    const int two_part = (out_size >= 2 * N_RAYS) ? 1 : 0;
    const int smem = (int)sizeof(SM);

    cudaFuncSetAttribute(nbvh_kernel, cudaFuncAttributeMaxDynamicSharedMemorySize, smem);

    nbvh_kernel<<<N_RAYS / RAYS_PB, THREADS, smem>>>(
        orig, vec, masks, t1, t2, mesh_min, mesh_max,
        W0, b0, ln_g, ln_b, Ws, bs, Wc, bc, Wd, bd,
        (float*)d_out, two_part);
}